// round 2
// baseline (speedup 1.0000x reference)
#include <cuda_runtime.h>

// SampleDepthwise: deformable-kernel depthwise conv.
// B=8, C=256, H=W=96, K=3 taps, S=4 scope, RG=1, PAD=1, stride 1.
//
// Key fact: rotation (bilinear positions) depends only on (b, tap, h, w),
// shared by all 256 channels. Per pixel we precompute, for each of 9 taps,
// 4 bilinear coefs (validity-masked) and one quad index into a padded
// per-channel 2x2-quad weight table held in shared memory. The channel loop
// then does, per channel and tap: 1x LDS.128 (quad) + 4 FMA (blend) +
// 1 predicated LDG (x patch) + 1 FMA (accumulate).

#define BN 8
#define CN 256
#define HN 96
#define WN 96
#define HW (HN * WN)

constexpr int CG = 64;            // channels per thread (loop)
constexpr int NCH = CN / CG;      // 4 channel chunks
constexpr int RPB = 2;            // h rows per block
constexpr int NQ = 35;            // quads per channel: y0 in [-2,4] (7) x x0 in [-1,3] (5)

__global__ __launch_bounds__(WN * RPB)
void sdw_kernel(const float* __restrict__ x,
                const float* __restrict__ rot,
                const float* __restrict__ wgt,
                float* __restrict__ out)
{
    __shared__ float4 sq[CG * NQ];   // 64 * 35 * 16B = 35840 B

    const int w  = threadIdx.x;                       // 0..95
    const int h  = blockIdx.x * RPB + threadIdx.y;    // 0..95
    const int b  = blockIdx.y;
    const int c0 = blockIdx.z * CG;

    // ---- Build padded quad table for this block's CG channels ----
    // Q[c][q] where q = (y0+2)*5 + (x0+1); entries are zero outside the 4x4 scope.
    {
        const int nth = WN * RPB;
        const int t = threadIdx.y * WN + threadIdx.x;
        for (int i = t; i < CG * NQ; i += nth) {
            const int c  = i / NQ;
            const int q  = i % NQ;
            const int y0 = q / 5 - 2;
            const int x0 = q % 5 - 1;
            const float* wc = wgt + (c0 + c) * 16;
            float v00 = (y0   >= 0 && y0   < 4 && x0   >= 0 && x0   < 4) ? __ldg(wc + y0 * 4 + x0)           : 0.f;
            float v01 = (y0   >= 0 && y0   < 4 && x0+1 >= 0 && x0+1 < 4) ? __ldg(wc + y0 * 4 + x0 + 1)       : 0.f;
            float v10 = (y0+1 >= 0 && y0+1 < 4 && x0   >= 0 && x0   < 4) ? __ldg(wc + (y0 + 1) * 4 + x0)     : 0.f;
            float v11 = (y0+1 >= 0 && y0+1 < 4 && x0+1 >= 0 && x0+1 < 4) ? __ldg(wc + (y0 + 1) * 4 + x0 + 1) : 0.f;
            sq[i] = make_float4(v00, v01, v10, v11);
        }
    }
    __syncthreads();

    // ---- Per-pixel tap precompute (amortized over CG channels) ----
    float c00[9], c01[9], c10[9], c11[9];
    int qidx[9];

    const float* rbase = rot + ((size_t)b * 18) * HW + (size_t)h * WN + w;

    #pragma unroll
    for (int kh = 0; kh < 3; kh++) {
        #pragma unroll
        for (int kw = 0; kw < 3; kw++) {
            const int tap = kh * 3 + kw;
            const float ry = __ldg(rbase + (2 * tap)     * HW);
            const float rx = __ldg(rbase + (2 * tap + 1) * HW);
            // (kh+0.5)*S/K - 0.5 computed in double then rounded to f32,
            // matching python-scalar + f32-array semantics.
            const float py = (float)((kh + 0.5) * 4.0 / 3.0 - 0.5) + ry;
            const float px = (float)((kw + 0.5) * 4.0 / 3.0 - 0.5) + rx;
            const float y0f = floorf(py), x0f = floorf(px);
            const float fy = py - y0f, fx = px - x0f;
            // If floor falls outside the padded table range, ALL corners are
            // invalid -> zero the coefs. Inside the range, padded zeros in the
            // quad table implement per-corner validity exactly.
            const float ymask = (y0f >= -2.f && y0f <= 4.f) ? 1.f : 0.f;
            const float xmask = (x0f >= -1.f && x0f <= 3.f) ? 1.f : 0.f;
            const float cy0 = (1.f - fy) * ymask, cy1 = fy * ymask;
            const float cx0 = (1.f - fx) * xmask, cx1 = fx * xmask;
            c00[tap] = cy0 * cx0; c01[tap] = cy0 * cx1;
            c10[tap] = cy1 * cx0; c11[tap] = cy1 * cx1;
            const float y0c = fminf(fmaxf(y0f, -2.f), 4.f);
            const float x0c = fminf(fmaxf(x0f, -1.f), 3.f);
            qidx[tap] = ((int)y0c + 2) * 5 + ((int)x0c + 1);
        }
    }

    // ---- x-patch spatial validity (channel-independent) ----
    bool pv[9];
    #pragma unroll
    for (int kh = 0; kh < 3; kh++) {
        #pragma unroll
        for (int kw = 0; kw < 3; kw++) {
            const int hh = h + kh - 1;
            const int ww = w + kw - 1;
            pv[kh * 3 + kw] = ((unsigned)hh < (unsigned)HN) && ((unsigned)ww < (unsigned)WN);
        }
    }

    // ---- Channel loop ----
    const size_t pix = (size_t)h * WN + w;
    const float* xp = x   + ((size_t)b * CN + c0) * HW + pix;
    float*       op = out + ((size_t)b * CN + c0) * HW + pix;
    const float4* qc = sq;

    #pragma unroll 2
    for (int ci = 0; ci < CG; ci++) {
        float xv[9];
        #pragma unroll
        for (int kh = 0; kh < 3; kh++) {
            #pragma unroll
            for (int kw = 0; kw < 3; kw++) {
                const int tap = kh * 3 + kw;
                xv[tap] = pv[tap] ? __ldg(xp + (kh - 1) * WN + (kw - 1)) : 0.f;
            }
        }
        float acc = 0.f;
        #pragma unroll
        for (int tap = 0; tap < 9; tap++) {
            const float4 q = qc[qidx[tap]];
            float g = c00[tap] * q.x;
            g = fmaf(c01[tap], q.y, g);
            g = fmaf(c10[tap], q.z, g);
            g = fmaf(c11[tap], q.w, g);
            acc = fmaf(g, xv[tap], acc);
        }
        *op = acc;
        xp += HW; op += HW; qc += NQ;
    }
}

extern "C" void kernel_launch(void* const* d_in, const int* in_sizes, int n_in,
                              void* d_out, int out_size)
{
    const float* x   = (const float*)d_in[0];
    const float* rot = (const float*)d_in[1];
    const float* wgt = (const float*)d_in[2];
    float* out = (float*)d_out;

    dim3 block(WN, RPB, 1);            // 96 x 2 = 192 threads
    dim3 grid(HN / RPB, BN, NCH);      // 48 x 8 x 4 = 1536 blocks
    sdw_kernel<<<grid, block>>>(x, rot, wgt, out);
}